// round 4
// baseline (speedup 1.0000x reference)
#include <cuda_runtime.h>
#include <math.h>

// PhasedLSTM B=256, T=1024, H=512 — single persistent kernel.
// Grid = 32 hidden-groups x 4 batch-groups = 128 CTAs (all co-resident on 148
// SMs, 1 CTA/SM by smem). Each CTA owns (64 batches x 16 hidden) and all 4
// gates for its slice; w_hh rows live in smem for the whole sequence. The
// T=1024 recurrence is synchronized by a software grid barrier (monotonic
// counter, reset by the init kernel each replay). Inner product uses
// fma.rn.f32x2 with lanes = (even k, odd k), reduced lo+hi at the end.

#define Bsz 256
#define Tsz 1024
#define Hsz 512
#define BT 64
#define HT 16
#define KC 64
#define NCH (Hsz / KC)        // 8
#define THREADS 256
#define GRIDX (Hsz / HT)      // 32
#define GRIDY (Bsz / BT)      // 4
#define NCTA (GRIDX * GRIDY)  // 128

#define WS_STRIDE 516         // 512 + 4 floats (129 float4 units, odd -> conflict-free)
#define HS_STRIDE 68          // 64 + 4 floats  (17 float4 units, odd)

// dynamic smem layout (float offsets)
#define OFF_WS   0
#define OFF_HS   (OFF_WS + 64 * WS_STRIDE)            // 33024
#define OFF_WIHB (OFF_HS + 2 * 64 * HS_STRIDE)        // +8704
#define OFF_TAUP (OFF_WIHB + 64 * 4)                  // +256
#define SMEM_FLOATS (OFF_TAUP + 16 * 2)
#define SMEM_BYTES (SMEM_FLOATS * 4)                  // ~168.2 KB

__device__ float g_h[2][Bsz * Hsz];
__device__ float g_c[2][Bsz * Hsz];
__device__ unsigned g_bar_cnt;
__device__ unsigned g_bar_gen;

__global__ void init_kernel() {
    int i = blockIdx.x * blockDim.x + threadIdx.x;
    if (i < Bsz * Hsz) { g_h[0][i] = 0.0f; g_c[0][i] = 0.0f; }
    if (i == 0) { g_bar_cnt = 0u; g_bar_gen = 0u; }
}

__device__ __forceinline__ unsigned long long ffma2(unsigned long long a,
                                                    unsigned long long b,
                                                    unsigned long long c) {
    unsigned long long d;
    asm("fma.rn.f32x2 %0, %1, %2, %3;" : "=l"(d) : "l"(a), "l"(b), "l"(c));
    return d;
}

__device__ __forceinline__ float2 ull2f2(unsigned long long u) {
    float2 f;
    asm("mov.b64 {%0, %1}, %2;" : "=f"(f.x), "=f"(f.y) : "l"(u));
    return f;
}

__device__ __forceinline__ float sigmoidf_(float x) { return 1.0f / (1.0f + expf(-x)); }

__device__ __forceinline__ void grid_barrier(unsigned target_gen) {
    __syncthreads();
    if (threadIdx.x == 0) {
        __threadfence();
        unsigned arr = atomicAdd(&g_bar_cnt, 1u) + 1u;
        if (arr == target_gen * NCTA) {
            atomicExch(&g_bar_gen, target_gen);
        } else {
            while (*(volatile unsigned*)&g_bar_gen < target_gen) { }
        }
        __threadfence();
    }
    __syncthreads();
}

__global__ void __launch_bounds__(THREADS, 1)
phased_lstm_persistent(const float* __restrict__ inputs,
                       const int*   __restrict__ starts,
                       const float* __restrict__ w_ih,
                       const float* __restrict__ w_hh,
                       const float* __restrict__ b_ih,
                       const float* __restrict__ b_hh,
                       const float* __restrict__ tau,
                       const float* __restrict__ phase,
                       float* __restrict__ out_final)
{
    extern __shared__ float sm[];
    float* w_s  = sm + OFF_WS;    // [64 rows][WS_STRIDE]
    float* h_sA = sm + OFF_HS;    // [2][64][HS_STRIDE]
    float* wihb = sm + OFF_WIHB;  // [64][4]: wih0,wih1,wih2,bsum
    float* taup = sm + OFF_TAUP;  // [16][2]: tau, phase

    const int tid = threadIdx.x;
    const int j0  = blockIdx.x * HT;
    const int b0  = blockIdx.y * BT;
    const int bq  = tid & 15;     // batch lane: batches b0 + bq + 16*i
    const int jq  = tid >> 4;     // hidden index jj (0..15); rows g*16+jq
    const int sb  = tid >> 2;     // staging batch 0..63
    const int sq  = tid & 3;      // staging quarter

    // ---- one-time staging: weights, epilogue constants ----
    for (int idx = tid; idx < 64 * 128; idx += THREADS) {   // 64 rows x 128 float4
        int r  = idx >> 7;
        int k4 = idx & 127;
        int grow = ((r >> 4) * Hsz) + j0 + (r & 15);
        float4 v = *(const float4*)&w_hh[(size_t)grow * Hsz + k4 * 4];
        *(float4*)&w_s[r * WS_STRIDE + k4 * 4] = v;
    }
    if (tid < 64) {
        int r = tid;
        int grow = ((r >> 4) * Hsz) + j0 + (r & 15);
        wihb[r * 4 + 0] = w_ih[grow * 3 + 0];
        wihb[r * 4 + 1] = w_ih[grow * 3 + 1];
        wihb[r * 4 + 2] = w_ih[grow * 3 + 2];
        wihb[r * 4 + 3] = b_ih[grow] + b_hh[grow];
    }
    if (tid < 16) {
        taup[tid * 2 + 0] = tau[j0 + tid];
        taup[tid * 2 + 1] = phase[j0 + tid];
    }
    int st[4];
    #pragma unroll
    for (int i = 0; i < 4; i++) st[i] = starts[b0 + bq + 16 * i];
    __syncthreads();

    for (int t = 0; t < Tsz; t++) {
        const int cur = t & 1;
        const float* __restrict__ h_in = g_h[cur];
        const float* __restrict__ c_in = g_c[cur];
        float* __restrict__ h_out = (t == Tsz - 1) ? out_final : g_h[cur ^ 1];
        float* __restrict__ c_out = g_c[cur ^ 1];

        // per-step prefetch: x, own-cell h0/c0 (latency hidden by FMA loop)
        float4 xv[4]; float h0v[4], c0v[4];
        #pragma unroll
        for (int i = 0; i < 4; i++) {
            const int b = b0 + bq + 16 * i;
            xv[i]  = *(const float4*)&inputs[((size_t)b * Tsz + t) * 4];
            h0v[i] = h_in[(size_t)b * Hsz + j0 + jq];
            c0v[i] = c_in[(size_t)b * Hsz + j0 + jq];
        }

        unsigned long long acc2[4][4];    // [batch i][gate], lanes = (even k, odd k)
        #pragma unroll
        for (int i = 0; i < 4; i++)
            #pragma unroll
            for (int g = 0; g < 4; g++) acc2[i][g] = 0ull;

        // stage chunk 0
        float4 pv[4];
        #pragma unroll
        for (int m = 0; m < 4; m++)
            pv[m] = *(const float4*)&h_in[(size_t)(b0 + sb) * Hsz + (sq * 4 + m) * 4];
        #pragma unroll
        for (int m = 0; m < 4; m++)
            *(float4*)&h_sA[sb * HS_STRIDE + (sq * 4 + m) * 4] = pv[m];
        __syncthreads();

        for (int kc = 0; kc < NCH; kc++) {
            if (kc + 1 < NCH) {
                #pragma unroll
                for (int m = 0; m < 4; m++)
                    pv[m] = *(const float4*)&h_in[(size_t)(b0 + sb) * Hsz
                                                  + (kc + 1) * KC + (sq * 4 + m) * 4];
            }
            const float* hb = h_sA + (kc & 1) * 64 * HS_STRIDE;
            const float* wb = w_s + kc * KC;

            #pragma unroll 4
            for (int k4 = 0; k4 < KC / 4; k4++) {
                ulonglong2 wv[4], hv[4];
                #pragma unroll
                for (int g = 0; g < 4; g++)
                    wv[g] = *(const ulonglong2*)&wb[(g * 16 + jq) * WS_STRIDE + k4 * 4];
                #pragma unroll
                for (int i = 0; i < 4; i++)
                    hv[i] = *(const ulonglong2*)&hb[(bq + 16 * i) * HS_STRIDE + k4 * 4];
                #pragma unroll
                for (int i = 0; i < 4; i++)
                    #pragma unroll
                    for (int g = 0; g < 4; g++) {
                        acc2[i][g] = ffma2(hv[i].x, wv[g].x, acc2[i][g]);
                        acc2[i][g] = ffma2(hv[i].y, wv[g].y, acc2[i][g]);
                    }
            }

            if (kc + 1 < NCH) {
                float* hw = h_sA + ((kc + 1) & 1) * 64 * HS_STRIDE;
                #pragma unroll
                for (int m = 0; m < 4; m++)
                    *(float4*)&hw[sb * HS_STRIDE + (sq * 4 + m) * 4] = pv[m];
                __syncthreads();
            }
        }

        // ---- epilogue: x-proj + biases + LSTM cell + phased update ----
        const float tj  = taup[jq * 2 + 0];
        const float phv = taup[jq * 2 + 1];
        #pragma unroll
        for (int i = 0; i < 4; i++) {
            const int b = b0 + bq + 16 * i;
            const float x0 = xv[i].x, x1 = xv[i].y, tsv = xv[i].z, x2 = xv[i].w;
            const bool active = (t >= st[i]);
            float pre[4];
            #pragma unroll
            for (int g = 0; g < 4; g++) {
                const int r = g * 16 + jq;
                float2 p = ull2f2(acc2[i][g]);
                pre[g] = p.x + p.y
                       + x0 * wihb[r * 4 + 0] + x1 * wihb[r * 4 + 1]
                       + x2 * wihb[r * 4 + 2] + wihb[r * 4 + 3];
            }
            const float iv = sigmoidf_(pre[0]);
            const float fv = sigmoidf_(pre[1]);
            const float gv = tanhf(pre[2]);
            const float ov = sigmoidf_(pre[3]);

            float cv = fv * c0v[i] + iv * gv;
            float hv = ov * tanhf(cv);
            if (!active) { cv = c0v[i]; hv = h0v[i]; }

            const float phi  = fabsf(fmodf(tsv - phv, tj)) / tj;
            const float k_up = phi * 40.0f;          // 2*phi/RATIO_ON
            float kk;
            if (phi < 0.025f)      kk = k_up;
            else if (phi < 0.05f)  kk = 2.0f - k_up;
            else                   kk = 0.001f * phi; // LEAK*phi

            const size_t idx = (size_t)b * Hsz + j0 + jq;
            c_out[idx] = kk * cv + (1.0f - kk) * c0v[i];
            h_out[idx] = kk * hv + (1.0f - kk) * h0v[i];
        }

        grid_barrier((unsigned)(t + 1));
    }
}

extern "C" void kernel_launch(void* const* d_in, const int* in_sizes, int n_in,
                              void* d_out, int out_size) {
    (void)in_sizes; (void)n_in; (void)out_size;
    const float* inputs = (const float*)d_in[0];
    const int*   starts = (const int*)  d_in[1];
    const float* w_ih   = (const float*)d_in[2];
    const float* w_hh   = (const float*)d_in[3];
    const float* b_ih   = (const float*)d_in[4];
    const float* b_hh   = (const float*)d_in[5];
    const float* tau    = (const float*)d_in[6];
    const float* phase  = (const float*)d_in[7];
    float* out = (float*)d_out;

    cudaFuncSetAttribute(phased_lstm_persistent,
                         cudaFuncAttributeMaxDynamicSharedMemorySize, SMEM_BYTES);

    init_kernel<<<(Bsz * Hsz + 255) / 256, 256>>>();

    dim3 grid(GRIDX, GRIDY);
    phased_lstm_persistent<<<grid, THREADS, SMEM_BYTES>>>(
        inputs, starts, w_ih, w_hh, b_ih, b_hh, tau, phase, out);
}

// round 6
// speedup vs baseline: 1.0112x; 1.0112x over previous
#include <cuda_runtime.h>
#include <math.h>

// PhasedLSTM B=256,T=1024,H=512 — persistent kernel, 128 CTAs, 512 thr/CTA.
// CTA = 64 batches x 16 hidden (64 gate-rows). w_hh resident in smem (gate-
// permuted rows), h staged per 64-k chunk (double buffer). Warp operand
// sharing: lanes = 8 batches x 4 j-slots -> 1-phase LDS.128 for both h and w.
// FFMA2 (fma.rn.f32x2) packs even/odd k. Per-step grid barrier.
// (Round-5 resubmission: Round-4 proposal never ran — container failure.)

#define Bsz 256
#define Tsz 1024
#define Hsz 512
#define KC 64
#define NCH 8
#define THREADS 512
#define GRIDX 32
#define GRIDY 4
#define NCTA 128

#define WS_STRIDE 516   // floats; 129 16B-units (mod 8 = 1 -> conflict-free)
#define HS_STRIDE 68    // floats; 17 16B-units
#define TIL_STRIDE 17

// dynamic smem layout (float offsets)
#define OFF_WS   0
#define OFF_HS   (OFF_WS + 64 * WS_STRIDE)
#define OFF_EH0  (OFF_HS + 2 * 64 * HS_STRIDE)
#define OFF_EC0  (OFF_EH0 + 64 * TIL_STRIDE)
#define OFF_EHN  (OFF_EC0 + 64 * TIL_STRIDE)
#define OFF_ECN  (OFF_EHN + 64 * TIL_STRIDE)
#define OFF_WIHB (OFF_ECN + 64 * TIL_STRIDE)
#define OFF_TAUP (OFF_WIHB + 64 * 4)
#define SMEM_FLOATS (OFF_TAUP + 32)
#define SMEM_BYTES (SMEM_FLOATS * 4)   // ~185.5 KB

__device__ float g_h[2][Bsz * Hsz];
__device__ float g_c[2][Bsz * Hsz];
__device__ float g_xT[Tsz * Bsz * 4];   // inputs transposed to [T][B][4]
__device__ unsigned g_bar_cnt;
__device__ unsigned g_bar_gen;

__global__ void init_kernel(const float* __restrict__ inputs) {
    int i = blockIdx.x * blockDim.x + threadIdx.x;
    if (i < Bsz * Hsz) { g_h[0][i] = 0.0f; g_c[0][i] = 0.0f; }
    if (i == 0) { g_bar_cnt = 0u; g_bar_gen = 0u; }
    // transpose x: [B][T][4] -> [T][B][4]
    for (int idx = i; idx < Bsz * Tsz; idx += gridDim.x * blockDim.x) {
        int b = idx >> 10, t = idx & 1023;
        float4 v = *(const float4*)&inputs[(size_t)idx * 4];
        *(float4*)&g_xT[((size_t)t * Bsz + b) * 4] = v;
    }
}

__device__ __forceinline__ unsigned long long ffma2(unsigned long long a,
                                                    unsigned long long b,
                                                    unsigned long long c) {
    unsigned long long d;
    asm("fma.rn.f32x2 %0, %1, %2, %3;" : "=l"(d) : "l"(a), "l"(b), "l"(c));
    return d;
}
__device__ __forceinline__ float2 ull2f2(unsigned long long u) {
    float2 f;
    asm("mov.b64 {%0, %1}, %2;" : "=f"(f.x), "=f"(f.y) : "l"(u));
    return f;
}
__device__ __forceinline__ float sig_fast(float x) {
    return 1.0f / (1.0f + __expf(-x));
}
__device__ __forceinline__ float tanh_fast(float x) {
    float e = __expf(-2.0f * fabsf(x));
    float r = __fdividef(1.0f - e, 1.0f + e);
    return copysignf(r, x);
}

__device__ __forceinline__ void grid_barrier(unsigned target_gen) {
    __syncthreads();
    if (threadIdx.x == 0) {
        __threadfence();
        unsigned arr = atomicAdd(&g_bar_cnt, 1u) + 1u;
        if (arr == target_gen * NCTA) {
            atomicExch(&g_bar_gen, target_gen);
        } else {
            while (*(volatile unsigned*)&g_bar_gen < target_gen) { }
        }
        __threadfence();
    }
    __syncthreads();
}

__global__ void __launch_bounds__(THREADS, 1)
phased_lstm_persistent(const int*   __restrict__ starts,
                       const float* __restrict__ w_ih,
                       const float* __restrict__ w_hh,
                       const float* __restrict__ b_ih,
                       const float* __restrict__ b_hh,
                       const float* __restrict__ tau,
                       const float* __restrict__ phase,
                       float* __restrict__ out_final)
{
    extern __shared__ float sm[];
    float* w_s  = sm + OFF_WS;
    float* h_sA = sm + OFF_HS;
    float* eh0  = sm + OFF_EH0;
    float* ec0  = sm + OFF_EC0;
    float* ehn  = sm + OFF_EHN;
    float* ecn  = sm + OFF_ECN;
    float* wihb = sm + OFF_WIHB;
    float* taup = sm + OFF_TAUP;

    const int tid  = threadIdx.x;
    const int j0   = blockIdx.x * 16;
    const int b0   = blockIdx.y * 64;
    const int lane = tid & 31;
    const int w    = tid >> 5;       // 0..15
    const int lb   = lane & 7;       // batch lane
    const int lr   = lane >> 3;      // j slot 0..3
    const int wbq  = w & 3;          // batch quarter
    const int wr4  = w >> 2;         // j quarter
    const int jloc = wr4 * 4 + lr;   // this thread's j (0..15)
    const int bA   = wbq * 16 + lb;  // CTA-local batches
    const int bB   = bA + 8;
    const int wrow = wr4 * 16 + lr;  // physical w row base (add 4*q)

    // staging lanes (h chunks)
    const int sb = tid >> 3;         // 0..63 batch
    const int sq = tid & 7;          // 8 x 2 float4 per batch-row

    // cooperative tile I/O lanes
    const int tj = tid & 15;
    const int tb = tid >> 4;         // 0..31

    // ---- one-time staging ----
    // w_hh rows: logical (g,j) -> physical (j>>2)*16 + (j&3) + 4g
    for (int idx = tid; idx < 64 * 128; idx += THREADS) {
        int r  = idx >> 7;           // logical row: g = r>>4, j = r&15
        int k4 = idx & 127;
        int g  = r >> 4, j = r & 15;
        int p  = (j >> 2) * 16 + (j & 3) + 4 * g;
        float4 v = *(const float4*)&w_hh[((size_t)(g * Hsz + j0 + j)) * Hsz + k4 * 4];
        *(float4*)&w_s[p * WS_STRIDE + k4 * 4] = v;
    }
    if (tid < 64) {
        int g = tid >> 4, j = tid & 15;
        int grow = g * Hsz + j0 + j;
        wihb[tid * 4 + 0] = w_ih[grow * 3 + 0];
        wihb[tid * 4 + 1] = w_ih[grow * 3 + 1];
        wihb[tid * 4 + 2] = w_ih[grow * 3 + 2];
        wihb[tid * 4 + 3] = b_ih[grow] + b_hh[grow];
    }
    if (tid < 16) {
        taup[tid * 2 + 0] = tau[j0 + tid];
        taup[tid * 2 + 1] = phase[j0 + tid];
    }
    const int stA = starts[b0 + bA];
    const int stB = starts[b0 + bB];
    __syncthreads();
    const float tj_v  = taup[jloc * 2 + 0];
    const float phs_v = taup[jloc * 2 + 1];

    for (int t = 0; t < Tsz; t++) {
        const int cur = t & 1;
        const float* __restrict__ h_in = g_h[cur];
        const float* __restrict__ c_in = g_c[cur];
        float* __restrict__ h_out = (t == Tsz - 1) ? out_final : g_h[cur ^ 1];
        float* __restrict__ c_out = g_c[cur ^ 1];

        // per-step staging: h0/c0 tiles (coalesced), chunk 0 of h, x regs
        #pragma unroll
        for (int m = 0; m < 2; m++) {
            int b = tb + 32 * m;
            eh0[b * TIL_STRIDE + tj] = h_in[(size_t)(b0 + b) * Hsz + j0 + tj];
            ec0[b * TIL_STRIDE + tj] = c_in[(size_t)(b0 + b) * Hsz + j0 + tj];
        }
        float4 pv[2];
        #pragma unroll
        for (int m = 0; m < 2; m++)
            pv[m] = *(const float4*)&h_in[(size_t)(b0 + sb) * Hsz + (sq * 2 + m) * 4];
        #pragma unroll
        for (int m = 0; m < 2; m++)
            *(float4*)&h_sA[sb * HS_STRIDE + (sq * 2 + m) * 4] = pv[m];

        const float4 xvA = *(const float4*)&g_xT[((size_t)t * Bsz + b0 + bA) * 4];
        const float4 xvB = *(const float4*)&g_xT[((size_t)t * Bsz + b0 + bB) * 4];
        __syncthreads();

        unsigned long long acc2[2][4];
        #pragma unroll
        for (int p = 0; p < 2; p++)
            #pragma unroll
            for (int q = 0; q < 4; q++) acc2[p][q] = 0ull;

        for (int kc = 0; kc < NCH; kc++) {
            if (kc + 1 < NCH) {
                #pragma unroll
                for (int m = 0; m < 2; m++)
                    pv[m] = *(const float4*)&h_in[(size_t)(b0 + sb) * Hsz
                                                  + (kc + 1) * KC + (sq * 2 + m) * 4];
            }
            const float* hb = h_sA + (kc & 1) * 64 * HS_STRIDE;
            const float* wb = w_s + kc * KC;

            #pragma unroll 4
            for (int k4 = 0; k4 < KC / 4; k4++) {
                ulonglong2 wv[4];
                #pragma unroll
                for (int q = 0; q < 4; q++)
                    wv[q] = *(const ulonglong2*)&wb[(wrow + 4 * q) * WS_STRIDE + k4 * 4];
                ulonglong2 hvA = *(const ulonglong2*)&hb[bA * HS_STRIDE + k4 * 4];
                ulonglong2 hvB = *(const ulonglong2*)&hb[bB * HS_STRIDE + k4 * 4];
                #pragma unroll
                for (int q = 0; q < 4; q++) {
                    acc2[0][q] = ffma2(hvA.x, wv[q].x, acc2[0][q]);
                    acc2[0][q] = ffma2(hvA.y, wv[q].y, acc2[0][q]);
                    acc2[1][q] = ffma2(hvB.x, wv[q].x, acc2[1][q]);
                    acc2[1][q] = ffma2(hvB.y, wv[q].y, acc2[1][q]);
                }
            }

            if (kc + 1 < NCH) {
                float* hw = h_sA + ((kc + 1) & 1) * 64 * HS_STRIDE;
                #pragma unroll
                for (int m = 0; m < 2; m++)
                    *(float4*)&hw[sb * HS_STRIDE + (sq * 2 + m) * 4] = pv[m];
            }
            __syncthreads();
        }

        // ---- epilogue: thread owns all 4 gates of (bA,jloc) and (bB,jloc) ----
        #pragma unroll
        for (int p = 0; p < 2; p++) {
            const int b = p ? bB : bA;
            const float4 xv = p ? xvB : xvA;
            const int st = p ? stB : stA;
            float pre[4];
            #pragma unroll
            for (int q = 0; q < 4; q++) {
                float2 s = ull2f2(acc2[p][q]);
                const float4 wb4 = *(const float4*)&wihb[(q * 16 + jloc) * 4];
                pre[q] = s.x + s.y + xv.x * wb4.x + xv.y * wb4.y + xv.w * wb4.z + wb4.w;
            }
            const float iv = sig_fast(pre[0]);
            const float fv = sig_fast(pre[1]);
            const float gv = tanh_fast(pre[2]);
            const float ov = sig_fast(pre[3]);

            const float c0v = ec0[b * TIL_STRIDE + jloc];
            const float h0v = eh0[b * TIL_STRIDE + jloc];
            float cv = fv * c0v + iv * gv;
            float hv = ov * tanh_fast(cv);
            if (t < st) { cv = c0v; hv = h0v; }

            const float phi  = fabsf(fmodf(xv.z - phs_v, tj_v)) / tj_v;
            const float k_up = phi * 40.0f;
            float kk;
            if (phi < 0.025f)      kk = k_up;
            else if (phi < 0.05f)  kk = 2.0f - k_up;
            else                   kk = 0.001f * phi;

            ecn[b * TIL_STRIDE + jloc] = kk * cv + (1.0f - kk) * c0v;
            ehn[b * TIL_STRIDE + jloc] = kk * hv + (1.0f - kk) * h0v;
        }
        __syncthreads();

        // cooperative coalesced write-out
        #pragma unroll
        for (int m = 0; m < 2; m++) {
            int b = tb + 32 * m;
            h_out[(size_t)(b0 + b) * Hsz + j0 + tj] = ehn[b * TIL_STRIDE + tj];
            c_out[(size_t)(b0 + b) * Hsz + j0 + tj] = ecn[b * TIL_STRIDE + tj];
        }

        grid_barrier((unsigned)(t + 1));
    }
}

extern "C" void kernel_launch(void* const* d_in, const int* in_sizes, int n_in,
                              void* d_out, int out_size) {
    (void)in_sizes; (void)n_in; (void)out_size;
    const float* inputs = (const float*)d_in[0];
    const int*   starts = (const int*)  d_in[1];
    const float* w_ih   = (const float*)d_in[2];
    const float* w_hh   = (const float*)d_in[3];
    const float* b_ih   = (const float*)d_in[4];
    const float* b_hh   = (const float*)d_in[5];
    const float* tau    = (const float*)d_in[6];
    const float* phase  = (const float*)d_in[7];
    float* out = (float*)d_out;

    cudaFuncSetAttribute(phased_lstm_persistent,
                         cudaFuncAttributeMaxDynamicSharedMemorySize, SMEM_BYTES);

    init_kernel<<<512, 256>>>(inputs);

    dim3 grid(GRIDX, GRIDY);
    phased_lstm_persistent<<<grid, THREADS, SMEM_BYTES>>>(
        starts, w_ih, w_hh, b_ih, b_hh, tau, phase, out);
}

// round 7
// speedup vs baseline: 1.0120x; 1.0008x over previous
#include <cuda_runtime.h>
#include <math.h>

// PhasedLSTM B=256,T=1024,H=512 — persistent kernel, 128 CTAs, 512 thr/CTA.
// CTA = 64 batches x 16 hidden (64 gate-rows). w_hh resident in smem (gate-
// permuted rows), h staged per 64-k chunk (double buffer). Warp operand
// sharing: lanes = 8 batches x 4 j-slots -> 1-phase LDS.128 for both h and w.
// FFMA2 (fma.rn.f32x2) packs even/odd k. Per-step grid barrier.
// (Round-5 resubmission: Round-4 proposal never ran — container failure.)

#define Bsz 256
#define Tsz 1024
#define Hsz 512
#define KC 64
#define NCH 8
#define THREADS 512
#define GRIDX 32
#define GRIDY 4
#define NCTA 128

#define WS_STRIDE 516   // floats; 129 16B-units (mod 8 = 1 -> conflict-free)
#define HS_STRIDE 68    // floats; 17 16B-units
#define TIL_STRIDE 17

// dynamic smem layout (float offsets)
#define OFF_WS   0
#define OFF_HS   (OFF_WS + 64 * WS_STRIDE)
#define OFF_EH0  (OFF_HS + 2 * 64 * HS_STRIDE)
#define OFF_EC0  (OFF_EH0 + 64 * TIL_STRIDE)
#define OFF_EHN  (OFF_EC0 + 64 * TIL_STRIDE)
#define OFF_ECN  (OFF_EHN + 64 * TIL_STRIDE)
#define OFF_WIHB (OFF_ECN + 64 * TIL_STRIDE)
#define OFF_TAUP (OFF_WIHB + 64 * 4)
#define SMEM_FLOATS (OFF_TAUP + 32)
#define SMEM_BYTES (SMEM_FLOATS * 4)   // ~185.5 KB

__device__ float g_h[2][Bsz * Hsz];
__device__ float g_c[2][Bsz * Hsz];
__device__ float g_xT[Tsz * Bsz * 4];   // inputs transposed to [T][B][4]
__device__ unsigned g_bar_cnt;
__device__ unsigned g_bar_gen;

__global__ void init_kernel(const float* __restrict__ inputs) {
    int i = blockIdx.x * blockDim.x + threadIdx.x;
    if (i < Bsz * Hsz) { g_h[0][i] = 0.0f; g_c[0][i] = 0.0f; }
    if (i == 0) { g_bar_cnt = 0u; g_bar_gen = 0u; }
    // transpose x: [B][T][4] -> [T][B][4]
    for (int idx = i; idx < Bsz * Tsz; idx += gridDim.x * blockDim.x) {
        int b = idx >> 10, t = idx & 1023;
        float4 v = *(const float4*)&inputs[(size_t)idx * 4];
        *(float4*)&g_xT[((size_t)t * Bsz + b) * 4] = v;
    }
}

__device__ __forceinline__ unsigned long long ffma2(unsigned long long a,
                                                    unsigned long long b,
                                                    unsigned long long c) {
    unsigned long long d;
    asm("fma.rn.f32x2 %0, %1, %2, %3;" : "=l"(d) : "l"(a), "l"(b), "l"(c));
    return d;
}
__device__ __forceinline__ float2 ull2f2(unsigned long long u) {
    float2 f;
    asm("mov.b64 {%0, %1}, %2;" : "=f"(f.x), "=f"(f.y) : "l"(u));
    return f;
}
__device__ __forceinline__ float sig_fast(float x) {
    return 1.0f / (1.0f + __expf(-x));
}
__device__ __forceinline__ float tanh_fast(float x) {
    float e = __expf(-2.0f * fabsf(x));
    float r = __fdividef(1.0f - e, 1.0f + e);
    return copysignf(r, x);
}

__device__ __forceinline__ void grid_barrier(unsigned target_gen) {
    __syncthreads();
    if (threadIdx.x == 0) {
        __threadfence();
        unsigned arr = atomicAdd(&g_bar_cnt, 1u) + 1u;
        if (arr == target_gen * NCTA) {
            atomicExch(&g_bar_gen, target_gen);
        } else {
            while (*(volatile unsigned*)&g_bar_gen < target_gen) { }
        }
        __threadfence();
    }
    __syncthreads();
}

__global__ void __launch_bounds__(THREADS, 1)
phased_lstm_persistent(const int*   __restrict__ starts,
                       const float* __restrict__ w_ih,
                       const float* __restrict__ w_hh,
                       const float* __restrict__ b_ih,
                       const float* __restrict__ b_hh,
                       const float* __restrict__ tau,
                       const float* __restrict__ phase,
                       float* __restrict__ out_final)
{
    extern __shared__ float sm[];
    float* w_s  = sm + OFF_WS;
    float* h_sA = sm + OFF_HS;
    float* eh0  = sm + OFF_EH0;
    float* ec0  = sm + OFF_EC0;
    float* ehn  = sm + OFF_EHN;
    float* ecn  = sm + OFF_ECN;
    float* wihb = sm + OFF_WIHB;
    float* taup = sm + OFF_TAUP;

    const int tid  = threadIdx.x;
    const int j0   = blockIdx.x * 16;
    const int b0   = blockIdx.y * 64;
    const int lane = tid & 31;
    const int w    = tid >> 5;       // 0..15
    const int lb   = lane & 7;       // batch lane
    const int lr   = lane >> 3;      // j slot 0..3
    const int wbq  = w & 3;          // batch quarter
    const int wr4  = w >> 2;         // j quarter
    const int jloc = wr4 * 4 + lr;   // this thread's j (0..15)
    const int bA   = wbq * 16 + lb;  // CTA-local batches
    const int bB   = bA + 8;
    const int wrow = wr4 * 16 + lr;  // physical w row base (add 4*q)

    // staging lanes (h chunks)
    const int sb = tid >> 3;         // 0..63 batch
    const int sq = tid & 7;          // 8 x 2 float4 per batch-row

    // cooperative tile I/O lanes
    const int tj = tid & 15;
    const int tb = tid >> 4;         // 0..31

    // ---- one-time staging ----
    // w_hh rows: logical (g,j) -> physical (j>>2)*16 + (j&3) + 4g
    for (int idx = tid; idx < 64 * 128; idx += THREADS) {
        int r  = idx >> 7;           // logical row: g = r>>4, j = r&15
        int k4 = idx & 127;
        int g  = r >> 4, j = r & 15;
        int p  = (j >> 2) * 16 + (j & 3) + 4 * g;
        float4 v = *(const float4*)&w_hh[((size_t)(g * Hsz + j0 + j)) * Hsz + k4 * 4];
        *(float4*)&w_s[p * WS_STRIDE + k4 * 4] = v;
    }
    if (tid < 64) {
        int g = tid >> 4, j = tid & 15;
        int grow = g * Hsz + j0 + j;
        wihb[tid * 4 + 0] = w_ih[grow * 3 + 0];
        wihb[tid * 4 + 1] = w_ih[grow * 3 + 1];
        wihb[tid * 4 + 2] = w_ih[grow * 3 + 2];
        wihb[tid * 4 + 3] = b_ih[grow] + b_hh[grow];
    }
    if (tid < 16) {
        taup[tid * 2 + 0] = tau[j0 + tid];
        taup[tid * 2 + 1] = phase[j0 + tid];
    }
    const int stA = starts[b0 + bA];
    const int stB = starts[b0 + bB];
    __syncthreads();
    const float tj_v  = taup[jloc * 2 + 0];
    const float phs_v = taup[jloc * 2 + 1];

    for (int t = 0; t < Tsz; t++) {
        const int cur = t & 1;
        const float* __restrict__ h_in = g_h[cur];
        const float* __restrict__ c_in = g_c[cur];
        float* __restrict__ h_out = (t == Tsz - 1) ? out_final : g_h[cur ^ 1];
        float* __restrict__ c_out = g_c[cur ^ 1];

        // per-step staging: h0/c0 tiles (coalesced), chunk 0 of h, x regs
        #pragma unroll
        for (int m = 0; m < 2; m++) {
            int b = tb + 32 * m;
            eh0[b * TIL_STRIDE + tj] = h_in[(size_t)(b0 + b) * Hsz + j0 + tj];
            ec0[b * TIL_STRIDE + tj] = c_in[(size_t)(b0 + b) * Hsz + j0 + tj];
        }
        float4 pv[2];
        #pragma unroll
        for (int m = 0; m < 2; m++)
            pv[m] = *(const float4*)&h_in[(size_t)(b0 + sb) * Hsz + (sq * 2 + m) * 4];
        #pragma unroll
        for (int m = 0; m < 2; m++)
            *(float4*)&h_sA[sb * HS_STRIDE + (sq * 2 + m) * 4] = pv[m];

        const float4 xvA = *(const float4*)&g_xT[((size_t)t * Bsz + b0 + bA) * 4];
        const float4 xvB = *(const float4*)&g_xT[((size_t)t * Bsz + b0 + bB) * 4];
        __syncthreads();

        unsigned long long acc2[2][4];
        #pragma unroll
        for (int p = 0; p < 2; p++)
            #pragma unroll
            for (int q = 0; q < 4; q++) acc2[p][q] = 0ull;

        for (int kc = 0; kc < NCH; kc++) {
            if (kc + 1 < NCH) {
                #pragma unroll
                for (int m = 0; m < 2; m++)
                    pv[m] = *(const float4*)&h_in[(size_t)(b0 + sb) * Hsz
                                                  + (kc + 1) * KC + (sq * 2 + m) * 4];
            }
            const float* hb = h_sA + (kc & 1) * 64 * HS_STRIDE;
            const float* wb = w_s + kc * KC;

            #pragma unroll 4
            for (int k4 = 0; k4 < KC / 4; k4++) {
                ulonglong2 wv[4];
                #pragma unroll
                for (int q = 0; q < 4; q++)
                    wv[q] = *(const ulonglong2*)&wb[(wrow + 4 * q) * WS_STRIDE + k4 * 4];
                ulonglong2 hvA = *(const ulonglong2*)&hb[bA * HS_STRIDE + k4 * 4];
                ulonglong2 hvB = *(const ulonglong2*)&hb[bB * HS_STRIDE + k4 * 4];
                #pragma unroll
                for (int q = 0; q < 4; q++) {
                    acc2[0][q] = ffma2(hvA.x, wv[q].x, acc2[0][q]);
                    acc2[0][q] = ffma2(hvA.y, wv[q].y, acc2[0][q]);
                    acc2[1][q] = ffma2(hvB.x, wv[q].x, acc2[1][q]);
                    acc2[1][q] = ffma2(hvB.y, wv[q].y, acc2[1][q]);
                }
            }

            if (kc + 1 < NCH) {
                float* hw = h_sA + ((kc + 1) & 1) * 64 * HS_STRIDE;
                #pragma unroll
                for (int m = 0; m < 2; m++)
                    *(float4*)&hw[sb * HS_STRIDE + (sq * 2 + m) * 4] = pv[m];
            }
            __syncthreads();
        }

        // ---- epilogue: thread owns all 4 gates of (bA,jloc) and (bB,jloc) ----
        #pragma unroll
        for (int p = 0; p < 2; p++) {
            const int b = p ? bB : bA;
            const float4 xv = p ? xvB : xvA;
            const int st = p ? stB : stA;
            float pre[4];
            #pragma unroll
            for (int q = 0; q < 4; q++) {
                float2 s = ull2f2(acc2[p][q]);
                const float4 wb4 = *(const float4*)&wihb[(q * 16 + jloc) * 4];
                pre[q] = s.x + s.y + xv.x * wb4.x + xv.y * wb4.y + xv.w * wb4.z + wb4.w;
            }
            const float iv = sig_fast(pre[0]);
            const float fv = sig_fast(pre[1]);
            const float gv = tanh_fast(pre[2]);
            const float ov = sig_fast(pre[3]);

            const float c0v = ec0[b * TIL_STRIDE + jloc];
            const float h0v = eh0[b * TIL_STRIDE + jloc];
            float cv = fv * c0v + iv * gv;
            float hv = ov * tanh_fast(cv);
            if (t < st) { cv = c0v; hv = h0v; }

            const float phi  = fabsf(fmodf(xv.z - phs_v, tj_v)) / tj_v;
            const float k_up = phi * 40.0f;
            float kk;
            if (phi < 0.025f)      kk = k_up;
            else if (phi < 0.05f)  kk = 2.0f - k_up;
            else                   kk = 0.001f * phi;

            ecn[b * TIL_STRIDE + jloc] = kk * cv + (1.0f - kk) * c0v;
            ehn[b * TIL_STRIDE + jloc] = kk * hv + (1.0f - kk) * h0v;
        }
        __syncthreads();

        // cooperative coalesced write-out
        #pragma unroll
        for (int m = 0; m < 2; m++) {
            int b = tb + 32 * m;
            h_out[(size_t)(b0 + b) * Hsz + j0 + tj] = ehn[b * TIL_STRIDE + tj];
            c_out[(size_t)(b0 + b) * Hsz + j0 + tj] = ecn[b * TIL_STRIDE + tj];
        }

        grid_barrier((unsigned)(t + 1));
    }
}

extern "C" void kernel_launch(void* const* d_in, const int* in_sizes, int n_in,
                              void* d_out, int out_size) {
    (void)in_sizes; (void)n_in; (void)out_size;
    const float* inputs = (const float*)d_in[0];
    const int*   starts = (const int*)  d_in[1];
    const float* w_ih   = (const float*)d_in[2];
    const float* w_hh   = (const float*)d_in[3];
    const float* b_ih   = (const float*)d_in[4];
    const float* b_hh   = (const float*)d_in[5];
    const float* tau    = (const float*)d_in[6];
    const float* phase  = (const float*)d_in[7];
    float* out = (float*)d_out;

    cudaFuncSetAttribute(phased_lstm_persistent,
                         cudaFuncAttributeMaxDynamicSharedMemorySize, SMEM_BYTES);

    init_kernel<<<512, 256>>>(inputs);

    dim3 grid(GRIDX, GRIDY);
    phased_lstm_persistent<<<grid, THREADS, SMEM_BYTES>>>(
        starts, w_ih, w_hh, b_ih, b_hh, tau, phase, out);
}

// round 9
// speedup vs baseline: 2.4280x; 2.3993x over previous
#include <cuda_runtime.h>
#include <cuda_bf16.h>
#include <math.h>
#include <stdint.h>

// PhasedLSTM B=256,T=1024,H=512 — persistent warp-MMA tensor-core kernel.
// sm_100 (non-'a') target: tcgen05 unavailable -> ldmatrix + mma.sync path.
// 128 CTAs = 4 M-tiles(64 batch) x 32 N-tiles(64 gate-rows = 16 j x 4 gates).
// preact = h @ w_hh^T via split-bf16 (hi+lo), 3 mma products -> fp32-grade.
// w hi/lo resident in smem; h hi/lo (bf16 ping-pong global) streamed in 8
// double-buffered K-chunks. Per-warp tile m32n16. Preact staged through smem
// so the LSTM/phased epilogue is thread-local. Grid barrier per step.

#define Bsz 256
#define Tsz 1024
#define Hsz 512
#define THREADS 256
#define NCTA 128
#define NCHUNK 8

// smem byte offsets
#define OFF_W    0                            // w_s[hl][kc][64 n][144B]
#define W_HL_STR 73728
#define W_KC_STR 9216
#define OFF_A    147456                       // a_s[buf][hl][64 row][144B]
#define A_BUF_STR 18432
#define A_HL_STR  9216
#define OFF_PRE  184320                       // preact [64][68] fp32
#define OFF_CST  201728                       // c_state [64][17] fp32
#define OFF_HST  206080                       // h_state [64][17] fp32
#define OFF_WIHB 210432                       // [64 n][4] fp32
#define OFF_TAUP 211456                       // [16][2] fp32
#define SMEM_BYTES 211584

__device__ __nv_bfloat16 g_whi[2048 * Hsz];
__device__ __nv_bfloat16 g_wlo[2048 * Hsz];
__device__ __nv_bfloat16 g_hhi[2][Bsz * Hsz];
__device__ __nv_bfloat16 g_hlo[2][Bsz * Hsz];
__device__ float g_xT[Tsz * Bsz * 4];
__device__ unsigned g_bar_cnt;
__device__ unsigned g_bar_gen;

__global__ void init_kernel(const float* __restrict__ inputs,
                            const float* __restrict__ w_hh) {
    int i = blockIdx.x * blockDim.x + threadIdx.x;
    int nthr = gridDim.x * blockDim.x;
    if (i == 0) { g_bar_cnt = 0u; g_bar_gen = 0u; }
    for (int idx = i; idx < 2048 * Hsz; idx += nthr) {
        float w = w_hh[idx];
        __nv_bfloat16 hi = __float2bfloat16(w);
        g_whi[idx] = hi;
        g_wlo[idx] = __float2bfloat16(w - __bfloat162float(hi));
    }
    for (int idx = i; idx < Bsz * Hsz; idx += nthr) {
        g_hhi[0][idx] = __float2bfloat16(0.0f);
        g_hlo[0][idx] = __float2bfloat16(0.0f);
    }
    for (int idx = i; idx < Bsz * Tsz; idx += nthr) {
        int b = idx >> 10, t = idx & 1023;
        float4 v = *(const float4*)&inputs[(size_t)idx * 4];
        *(float4*)&g_xT[((size_t)t * Bsz + b) * 4] = v;
    }
}

__device__ __forceinline__ uint32_t smem_u32(const void* p) {
    uint32_t a;
    asm("{ .reg .u64 t; cvta.to.shared.u64 t, %1; cvt.u32.u64 %0, t; }"
        : "=r"(a) : "l"(p));
    return a;
}
__device__ __forceinline__ void ldm4(uint32_t* r, uint32_t addr) {
    asm volatile("ldmatrix.sync.aligned.m8n8.x4.shared.b16 {%0,%1,%2,%3}, [%4];"
                 : "=r"(r[0]), "=r"(r[1]), "=r"(r[2]), "=r"(r[3]) : "r"(addr));
}
__device__ __forceinline__ void mma16816(float* d, const uint32_t* a,
                                         const uint32_t* b) {
    asm volatile("mma.sync.aligned.m16n8k16.row.col.f32.bf16.bf16.f32 "
                 "{%0,%1,%2,%3}, {%4,%5,%6,%7}, {%8,%9}, {%0,%1,%2,%3};"
                 : "+f"(d[0]), "+f"(d[1]), "+f"(d[2]), "+f"(d[3])
                 : "r"(a[0]), "r"(a[1]), "r"(a[2]), "r"(a[3]),
                   "r"(b[0]), "r"(b[1]));
}
__device__ __forceinline__ float sig_fast(float x) { return 1.0f / (1.0f + __expf(-x)); }
__device__ __forceinline__ float tanh_fast(float x) {
    float e = __expf(-2.0f * fabsf(x));
    float r = __fdividef(1.0f - e, 1.0f + e);
    return copysignf(r, x);
}
__device__ __forceinline__ void grid_barrier(unsigned target_gen) {
    __syncthreads();
    if (threadIdx.x == 0) {
        __threadfence();
        unsigned arr = atomicAdd(&g_bar_cnt, 1u) + 1u;
        if (arr == target_gen * NCTA) {
            atomicExch(&g_bar_gen, target_gen);
        } else {
            while (*(volatile unsigned*)&g_bar_gen < target_gen) { }
        }
        __threadfence();
    }
    __syncthreads();
}

__global__ void __launch_bounds__(THREADS, 1)
plstm_mma(const int*   __restrict__ starts,
          const float* __restrict__ w_ih,
          const float* __restrict__ b_ih,
          const float* __restrict__ b_hh,
          const float* __restrict__ tau,
          const float* __restrict__ phase,
          float* __restrict__ out_final)
{
    extern __shared__ __align__(16) char smem[];
    const uint32_t sbase = smem_u32(smem);
    float* preact = (float*)(smem + OFF_PRE);   // [64][68]
    float* c_st   = (float*)(smem + OFF_CST);   // [64][17]
    float* h_st   = (float*)(smem + OFF_HST);
    float* wihb   = (float*)(smem + OFF_WIHB);  // [64 n][4]

    const int tid    = threadIdx.x;
    const int lane   = tid & 31;
    const int warp   = tid >> 5;
    const int warp_m = warp >> 2;               // 0..1 (batch half)
    const int warp_n = warp & 3;                // 0..3 (n16 group)
    const int g8     = lane >> 2;               // mma group id
    const int t4     = lane & 3;
    const int j0     = blockIdx.x * 16;         // hidden base
    const int b0     = blockIdx.y * 64;         // batch base

    // ldmatrix per-thread address components
    const uint32_t aoff = (uint32_t)((warp_m * 32 + (lane & 15)) * 144
                                     + ((lane >> 4) * 16));
    const int n_off = (lane & 7) + ((lane >> 4) << 3);
    const uint32_t boff = (uint32_t)((warp_n * 16 + n_off) * 144
                                     + (((lane >> 3) & 1) * 16));

    // epilogue mapping: thread -> batch b, 4 consecutive j
    const int eb   = tid & 63;
    const int jgrp = tid >> 6;                  // 0..3

    // staging mapping: 16B unit u -> row=u>>3, c16=u&7
    // ---- one-time staging ----
    for (int hl = 0; hl < 2; hl++) {
        const __nv_bfloat16* src = hl ? g_wlo : g_whi;
        char* dstb = smem + OFF_W + hl * W_HL_STR;
        for (int u = tid; u < 64 * 64; u += THREADS) {   // 64 n x 64 c16
            int n = u >> 6, c16 = u & 63;
            int r = (n & 3) * Hsz + j0 + (n >> 2);       // n = j*4+g
            uint4 v = *(const uint4*)&src[(size_t)r * Hsz + c16 * 8];
            int kc = c16 >> 3, cc = c16 & 7;
            *(uint4*)(dstb + kc * W_KC_STR + n * 144 + cc * 16) = v;
        }
    }
    for (int n = tid; n < 64; n += THREADS) {
        int r = (n & 3) * Hsz + j0 + (n >> 2);
        wihb[n * 4 + 0] = w_ih[r * 3 + 0];
        wihb[n * 4 + 1] = w_ih[r * 3 + 1];
        wihb[n * 4 + 2] = w_ih[r * 3 + 2];
        wihb[n * 4 + 3] = b_ih[r] + b_hh[r];
    }
    for (int u = tid; u < 64 * 17; u += THREADS) { c_st[u] = 0.0f; h_st[u] = 0.0f; }

    float tau_r[4], phs_r[4];
    #pragma unroll
    for (int jj = 0; jj < 4; jj++) {
        tau_r[jj] = tau[j0 + jgrp * 4 + jj];
        phs_r[jj] = phase[j0 + jgrp * 4 + jj];
    }
    const int stb = starts[b0 + eb];
    __syncthreads();

    for (int t = 0; t < Tsz; t++) {
        const int rb = t & 1, wb = rb ^ 1;
        const __nv_bfloat16* __restrict__ hhi = g_hhi[rb];
        const __nv_bfloat16* __restrict__ hlo = g_hlo[rb];

        const float4 xv = *(const float4*)&g_xT[((size_t)t * Bsz + b0 + eb) * 4];

        float acc[2][2][4];
        #pragma unroll
        for (int mi = 0; mi < 2; mi++)
            #pragma unroll
            for (int ni = 0; ni < 2; ni++)
                #pragma unroll
                for (int e = 0; e < 4; e++) acc[mi][ni][e] = 0.0f;

        // stage chunk 0
        {
            #pragma unroll
            for (int hl = 0; hl < 2; hl++) {
                const __nv_bfloat16* src = hl ? hlo : hhi;
                char* dstb = smem + OFF_A + hl * A_HL_STR;
                #pragma unroll
                for (int i = 0; i < 2; i++) {
                    int u = tid + THREADS * i;
                    int row = u >> 3, c16 = u & 7;
                    uint4 v = *(const uint4*)&src[(size_t)(b0 + row) * Hsz + c16 * 8];
                    *(uint4*)(dstb + row * 144 + c16 * 16) = v;
                }
            }
        }
        __syncthreads();

        for (int kc = 0; kc < NCHUNK; kc++) {
            const int buf = kc & 1;
            uint4 pv[2][2];
            if (kc + 1 < NCHUNK) {
                #pragma unroll
                for (int hl = 0; hl < 2; hl++) {
                    const __nv_bfloat16* src = hl ? hlo : hhi;
                    #pragma unroll
                    for (int i = 0; i < 2; i++) {
                        int u = tid + THREADS * i;
                        int row = u >> 3, c16 = u & 7;
                        pv[hl][i] = *(const uint4*)&src[(size_t)(b0 + row) * Hsz
                                                        + (kc + 1) * 64 + c16 * 8];
                    }
                }
            }

            const uint32_t abase = sbase + OFF_A + buf * A_BUF_STR + aoff;
            const uint32_t bbase = sbase + OFF_W + kc * W_KC_STR + boff;
            #pragma unroll
            for (int ks = 0; ks < 4; ks++) {
                uint32_t ahi[2][4], alo[2][4], bhi[4], blo[4];
                ldm4(ahi[0], abase + ks * 32);
                ldm4(ahi[1], abase + ks * 32 + 16 * 144);
                ldm4(alo[0], abase + A_HL_STR + ks * 32);
                ldm4(alo[1], abase + A_HL_STR + ks * 32 + 16 * 144);
                ldm4(bhi, bbase + ks * 32);
                ldm4(blo, bbase + W_HL_STR + ks * 32);
                #pragma unroll
                for (int mi = 0; mi < 2; mi++)
                    #pragma unroll
                    for (int ni = 0; ni < 2; ni++) {
                        mma16816(acc[mi][ni], ahi[mi], bhi + 2 * ni);
                        mma16816(acc[mi][ni], ahi[mi], blo + 2 * ni);
                        mma16816(acc[mi][ni], alo[mi], bhi + 2 * ni);
                    }
            }

            if (kc + 1 < NCHUNK) {
                const int nbuf = buf ^ 1;
                #pragma unroll
                for (int hl = 0; hl < 2; hl++) {
                    char* dstb = smem + OFF_A + nbuf * A_BUF_STR + hl * A_HL_STR;
                    #pragma unroll
                    for (int i = 0; i < 2; i++) {
                        int u = tid + THREADS * i;
                        int row = u >> 3, c16 = u & 7;
                        *(uint4*)(dstb + row * 144 + c16 * 16) = pv[hl][i];
                    }
                }
            }
            __syncthreads();
        }

        // scatter accumulators to preact smem tile
        #pragma unroll
        for (int mi = 0; mi < 2; mi++)
            #pragma unroll
            for (int ni = 0; ni < 2; ni++) {
                const int row = warp_m * 32 + mi * 16 + g8;
                const int col = warp_n * 16 + ni * 8 + 2 * t4;
                *(float2*)&preact[row * 68 + col] =
                    make_float2(acc[mi][ni][0], acc[mi][ni][1]);
                *(float2*)&preact[(row + 8) * 68 + col] =
                    make_float2(acc[mi][ni][2], acc[mi][ni][3]);
            }
        __syncthreads();

        // ---- epilogue: thread = batch eb, j = j0 + jgrp*4 + jj ----
        union { __nv_bfloat16 h[4]; uint2 u; } phi_, plo_;
        float hs_out[4];
        #pragma unroll
        for (int jj = 0; jj < 4; jj++) {
            const int jl = jgrp * 4 + jj;
            const float4 pr = *(const float4*)&preact[eb * 68 + jl * 4];
            const float* prv = (const float*)&pr;
            float pre[4];
            #pragma unroll
            for (int g = 0; g < 4; g++) {
                const float4 wb4 = *(const float4*)&wihb[(jl * 4 + g) * 4];
                pre[g] = prv[g] + xv.x * wb4.x + xv.y * wb4.y
                       + xv.w * wb4.z + wb4.w;
            }
            const float iv = sig_fast(pre[0]);
            const float fv = sig_fast(pre[1]);
            const float gv = tanh_fast(pre[2]);
            const float ov = sig_fast(pre[3]);

            const float c0v = c_st[eb * 17 + jl];
            const float h0v = h_st[eb * 17 + jl];
            float cv = fv * c0v + iv * gv;
            float hv = ov * tanh_fast(cv);
            if (t < stb) { cv = c0v; hv = h0v; }

            const float phi = fabsf(fmodf(xv.z - phs_r[jj], tau_r[jj])) / tau_r[jj];
            const float k_up = phi * 40.0f;
            float kk;
            if (phi < 0.025f)      kk = k_up;
            else if (phi < 0.05f)  kk = 2.0f - k_up;
            else                   kk = 0.001f * phi;

            const float cs = kk * cv + (1.0f - kk) * c0v;
            const float hs = kk * hv + (1.0f - kk) * h0v;
            c_st[eb * 17 + jl] = cs;
            h_st[eb * 17 + jl] = hs;
            hs_out[jj] = hs;

            const __nv_bfloat16 hb = __float2bfloat16(hs);
            phi_.h[jj] = hb;
            plo_.h[jj] = __float2bfloat16(hs - __bfloat162float(hb));
        }
        const size_t gidx = (size_t)(b0 + eb) * Hsz + j0 + jgrp * 4;
        *(uint2*)&g_hhi[wb][gidx] = phi_.u;
        *(uint2*)&g_hlo[wb][gidx] = plo_.u;
        if (t == Tsz - 1)
            *(float4*)&out_final[gidx] = make_float4(hs_out[0], hs_out[1],
                                                     hs_out[2], hs_out[3]);

        grid_barrier((unsigned)(t + 1));
    }
}

extern "C" void kernel_launch(void* const* d_in, const int* in_sizes, int n_in,
                              void* d_out, int out_size) {
    (void)in_sizes; (void)n_in; (void)out_size;
    const float* inputs = (const float*)d_in[0];
    const int*   starts = (const int*)  d_in[1];
    const float* w_ih   = (const float*)d_in[2];
    const float* w_hh   = (const float*)d_in[3];
    const float* b_ih   = (const float*)d_in[4];
    const float* b_hh   = (const float*)d_in[5];
    const float* tau    = (const float*)d_in[6];
    const float* phase  = (const float*)d_in[7];
    float* out = (float*)d_out;

    cudaFuncSetAttribute(plstm_mma,
                         cudaFuncAttributeMaxDynamicSharedMemorySize, SMEM_BYTES);

    init_kernel<<<512, 256>>>(inputs, w_hh);

    dim3 grid(32, 4);   // 32 N-tiles x 4 M-tiles = 128 CTAs
    plstm_mma<<<grid, THREADS, SMEM_BYTES>>>(starts, w_ih, b_ih, b_hh,
                                             tau, phase, out);
}